// round 10
// baseline (speedup 1.0000x reference)
#include <cuda_runtime.h>

// OrthonormalWaveletRegularization: L=32 -> scalar. All-fp32, 2 warps.
// R9: R8 minus the 4-deep serial post-transpose butterfly — even lanes STS
// their chain contribution straight into a 33-slot final row (conflict-free),
// one BAR, lane 0 tree-sums 8x LDS.128 and stores. l1 gets its own slot.

#define SQRT2F 1.41421356237309504880f

__global__ void owr_kernel(const float* __restrict__ h,
                           const float* __restrict__ g,
                           float* __restrict__ out) {
    const int tid = threadIdx.x;                 // 0..63
    const int w   = tid >> 5;
    const int l   = tid & 31;
    __shared__ __align__(16) float s[32][36];    // 32 chains, stride 36
    __shared__ __align__(16) float fin[36];      // 33 used: 32 chain terms + l1

    if (w == 0) {
        const float hv = h[l];
        // lag chains k=0..15 (rows 0..15): h[r]*h[r+2k]; k=0 gives h^2
        #pragma unroll
        for (int k = 0; k <= 15; ++k) {
            const int d = 2 * k;
            const float hs = __shfl_down_sync(0xFFFFFFFFu, hv, d);
            s[k][l] = (l + d < 32) ? hv * hs : 0.0f;
        }
        // Sum(h) butterfly — overlaps warp 1's power-chain build
        float s_h = hv;
        #pragma unroll
        for (int o = 16; o > 0; o >>= 1)
            s_h += __shfl_xor_sync(0xFFFFFFFFu, s_h, o);
        if (l == 0) {
            const float e1 = s_h - SQRT2F;
            fin[32] = e1 * e1;                   // l1
            fin[33] = 0.0f; fin[34] = 0.0f; fin[35] = 0.0f; // pad for LDS.128 tree
        }
    } else {
        const float gv = g[l];
        // moment chains p=1..16 (rows 16..31): r^(p-1)*g[r], log-depth powers
        const float r1 = (float)l;
        const float r2 = r1 * r1;
        const float r4 = r2 * r2;
        const float r8 = r4 * r4;
        float wt[16];
        wt[0]  = 1.0f;       wt[1]  = r1;           wt[2]  = r2;           wt[3]  = r2 * r1;
        wt[4]  = r4;         wt[5]  = r4 * r1;      wt[6]  = r4 * r2;      wt[7]  = wt[6] * r1;
        wt[8]  = r8;         wt[9]  = r8 * r1;      wt[10] = r8 * r2;      wt[11] = wt[10] * r1;
        wt[12] = r8 * r4;    wt[13] = wt[12] * r1;  wt[14] = wt[12] * r2;  wt[15] = wt[14] * r1;
        #pragma unroll
        for (int p = 1; p <= 16; ++p)
            s[15 + p][l] = wt[p - 1] * gv;
    }

    __syncthreads();

    // --- transpose: 2 lanes per chain; chain c = tid>>1 ---
    const int c  = tid >> 1;
    const int hh = tid & 1;
    const float4* row = (const float4*)s[c] + hh * 4;
    float x[4];
    #pragma unroll
    for (int i = 0; i < 4; ++i) {
        const float4 q = row[i];
        x[i] = (q.x + q.y) + (q.z + q.w);
    }
    float part = (x[0] + x[1]) + (x[2] + x[3]);
    part += __shfl_down_sync(0xFFFFFFFFu, part, 1);   // even lane: full chain sum

    if (hh == 0) {
        const float ssum = part;
        float contrib;
        if (c == 0) {
            const float e3 = ssum - 1.0f;             // lag0 = dot(h,h)
            contrib = e3 * e3;                        // l3
        } else if (c <= 15) {
            contrib = ssum * ssum;                    // l4 term (lag c)
        } else {
            const int p = c - 15;                     // 1..16
            if (p == 1) {
                contrib = 1.5f * ssum * ssum;         // l2 + p=1 l5 term
            } else {
                const float norm = SQRT2F * __int_as_float((127 - p) << 23); // sqrt2*2^-p
                const float m = ssum * norm;
                contrib = m * m;                      // l5 term
            }
        }
        fin[c] = contrib;                             // 32 distinct banks: conflict-free
    }

    __syncthreads();

    if (tid == 0) {
        const float4* fr = (const float4*)fin;        // 36 floats -> 9 float4 (33 live)
        float y[9];
        #pragma unroll
        for (int i = 0; i < 9; ++i) {
            const float4 q = fr[i];
            y[i] = (q.x + q.y) + (q.z + q.w);
        }
        out[0] = (((y[0] + y[1]) + (y[2] + y[3])) + ((y[4] + y[5]) + (y[6] + y[7]))) + y[8];
    }
}

extern "C" void kernel_launch(void* const* d_in, const int* in_sizes, int n_in,
                              void* d_out, int out_size) {
    const float* h = (const float*)d_in[0];
    const float* g = (const float*)d_in[1];
    float* out = (float*)d_out;
    owr_kernel<<<1, 64>>>(h, g, out);
}

// round 11
// speedup vs baseline: 1.0070x; 1.0070x over previous
#include <cuda_runtime.h>

// OrthonormalWaveletRegularization: L=32 -> scalar. One warp, all-fp32.
// R10 (final): minimal member of the R5/R7 family. 32 chains = 32 lanes
// (lag k=0..15, lag0 == dot(h,h); moments p=1..16), Sum(h) butterfly
// overlapped with STS, ONE syncwarp, LDS.128 transpose, 5-SHFL final
// butterfly, l1 folded in at lane 31. Kernel is overhead-bound (~T_ovh +
// cold LDG); four structural variants all pin wall at 4.58+-0.03us.

#define SQRT2F 1.41421356237309504880f

__global__ void owr_kernel(const float* __restrict__ h,
                           const float* __restrict__ g,
                           float* __restrict__ out) {
    const int t = threadIdx.x;                       // lane = element index r
    __shared__ __align__(16) float s[32][36];        // 32 chains, stride 36

    const float hv = h[t];
    const float gv = g[t];

    // --- moment chains p=1..16 (rows 16..31): r^(p-1)*g[r], log-depth powers ---
    {
        const float r1 = (float)t;
        const float r2 = r1 * r1;
        const float r4 = r2 * r2;
        const float r8 = r4 * r4;
        float w[16];
        w[0]  = 1.0f;        w[1]  = r1;          w[2]  = r2;          w[3]  = r2 * r1;
        w[4]  = r4;          w[5]  = r4 * r1;     w[6]  = r4 * r2;     w[7]  = w[6] * r1;
        w[8]  = r8;          w[9]  = r8 * r1;     w[10] = r8 * r2;     w[11] = w[10] * r1;
        w[12] = r8 * r4;     w[13] = w[12] * r1;  w[14] = w[12] * r2;  w[15] = w[14] * r1;
        #pragma unroll
        for (int p = 1; p <= 16; ++p)
            s[15 + p][t] = w[p - 1] * gv;
    }

    // --- lag chains k=0..15 (rows 0..15): h[r]*h[r+2k]; k=0 gives h^2 ---
    #pragma unroll
    for (int k = 0; k <= 15; ++k) {
        const int d = 2 * k;
        const float hs = __shfl_down_sync(0xFFFFFFFFu, hv, d);
        s[k][t] = (t + d < 32) ? hv * hs : 0.0f;
    }

    // --- Sum(h) butterfly: overlaps the STS drain above ---
    float s_h = hv;
    #pragma unroll
    for (int o = 16; o > 0; o >>= 1)
        s_h += __shfl_xor_sync(0xFFFFFFFFu, s_h, o);

    __syncwarp();

    // --- transpose: lane j tree-sums chain j with LDS.128 reads ---
    float ssum;
    {
        const float4* row = (const float4*)s[t];
        float x[8];
        #pragma unroll
        for (int i = 0; i < 8; ++i) {
            const float4 q = row[i];
            x[i] = (q.x + q.y) + (q.z + q.w);
        }
        ssum = ((x[0] + x[1]) + (x[2] + x[3])) + ((x[4] + x[5]) + (x[6] + x[7]));
    }

    // --- per-lane contribution ---
    float contrib;
    if (t == 0) {
        const float e3 = ssum - 1.0f;                                // lag0 = dot(h,h)
        contrib = e3 * e3;                                           // l3
    } else if (t <= 15) {
        contrib = ssum * ssum;                                       // l4 term (lag t)
    } else {
        const int p = t - 15;                                        // 1..16
        if (p == 1) {
            contrib = 1.5f * ssum * ssum;                            // l2 + p=1 l5 term
        } else {
            const float norm = SQRT2F * __int_as_float((127 - p) << 23); // sqrt2*2^-p
            const float m = ssum * norm;
            contrib = m * m;                                         // l5 term
        }
        if (t == 31) {
            const float e1 = s_h - SQRT2F;
            contrib += e1 * e1;                                      // l1
        }
    }

    // --- final 5-stage butterfly, lane 0 stores ---
    #pragma unroll
    for (int o = 16; o > 0; o >>= 1)
        contrib += __shfl_xor_sync(0xFFFFFFFFu, contrib, o);

    if (t == 0)
        out[0] = contrib;
}

extern "C" void kernel_launch(void* const* d_in, const int* in_sizes, int n_in,
                              void* d_out, int out_size) {
    const float* h = (const float*)d_in[0];
    const float* g = (const float*)d_in[1];
    float* out = (float*)d_out;
    owr_kernel<<<1, 32>>>(h, g, out);
}